// round 13
// baseline (speedup 1.0000x reference)
#include <cuda_runtime.h>

// ---------------------------------------------------------------------------
// Net_33071248179899: 2-layer LIF SNN, T=200, B=512, 784->1024->10
// Bitwise-replicate the reference dot fold. Evidence-driven hypothesis:
// Eigen single-threaded blocking heuristic rebalances K into ~equal panels:
//   K=784  -> kc=400 -> panels {400, 384}   (2 panels; my falsification
//             pattern shows output depends on panel count, with counts
//             {1,3}->A and {4}->B both wrong => ref has 2 panels)
//   K=1024 -> kc=344 -> panels {344, 344, 336}
// Per element: C = (p0 + p1) [+ p2], each pi an ascending-k fp32 FMA chain
// from 0; bias added once at the end.
// LIF: mem = ((beta*mem) + cur) - reset, each op individually rounded.
// ---------------------------------------------------------------------------

constexpr int T_STEPS = 200;
constexpr int BATCH   = 512;
constexpr int NIN     = 784;
constexpr int NHID    = 1024;
constexpr int NOUT    = 10;
constexpr int M_TOTAL = T_STEPS * BATCH;          // 102400
constexpr float BETA  = 0.95f;
constexpr int KC2     = 344;                       // Eigen single-thread kc, K=1024

// Scratch (device globals: allocation-free rule)
__device__ float    g_cur1[(size_t)M_TOTAL * NHID];           // ~420 MB
__device__ unsigned g_spk1[(size_t)M_TOTAL * (NHID / 32)];    // ~13 MB
__device__ float    g_cur2[(size_t)M_TOTAL * NOUT];           // ~4 MB

// ---------------------------------------------------------------------------
// GEMM1: Eigen-fold GEMM. Tiles 128x128x16, 256 threads, 8x8/thread,
// double-buffered smem. kc=400 boundary aligns to BK=16 tiles:
// fold after kt = 25 (k=400) and at the end (384-tail panel).
// ---------------------------------------------------------------------------
constexpr int BM = 128, BN = 128, BK = 16;
constexpr int NKT = NIN / BK;   // 49

__global__ void __launch_bounds__(256, 1)
gemm1_kernel(const float* __restrict__ A, const float* __restrict__ W,
             const float* __restrict__ bias)
{
    __shared__ float a_s[2][BK][BM + 4];
    __shared__ float b_s[2][BK][BN + 4];
    float* __restrict__ C = g_cur1;

    const int tid = threadIdx.x;
    const int bm = blockIdx.y * BM;
    const int bn = blockIdx.x * BN;

    const int lrow = tid >> 2;          // 0..63
    const int lk   = (tid & 3) * 4;     // 0,4,8,12

    const float* aP = A + (size_t)(bm + lrow) * NIN + lk;
    const float* bP = W + (size_t)(bn + lrow) * NIN + lk;

    float4 ra0, ra1, rb0, rb1;

    ra0 = *(const float4*)(aP);
    ra1 = *(const float4*)(aP + 64 * NIN);
    rb0 = *(const float4*)(bP);
    rb1 = *(const float4*)(bP + 64 * NIN);

    a_s[0][lk + 0][lrow] = ra0.x; a_s[0][lk + 1][lrow] = ra0.y;
    a_s[0][lk + 2][lrow] = ra0.z; a_s[0][lk + 3][lrow] = ra0.w;
    a_s[0][lk + 0][lrow + 64] = ra1.x; a_s[0][lk + 1][lrow + 64] = ra1.y;
    a_s[0][lk + 2][lrow + 64] = ra1.z; a_s[0][lk + 3][lrow + 64] = ra1.w;
    b_s[0][lk + 0][lrow] = rb0.x; b_s[0][lk + 1][lrow] = rb0.y;
    b_s[0][lk + 2][lrow] = rb0.z; b_s[0][lk + 3][lrow] = rb0.w;
    b_s[0][lk + 0][lrow + 64] = rb1.x; b_s[0][lk + 1][lrow + 64] = rb1.y;
    b_s[0][lk + 2][lrow + 64] = rb1.z; b_s[0][lk + 3][lrow + 64] = rb1.w;
    __syncthreads();

    float acc[8][8];   // current k-panel FMA chain
    float tot[8][8];   // running cross-panel sum (plain adds)
#pragma unroll
    for (int i = 0; i < 8; i++)
#pragma unroll
        for (int j = 0; j < 8; j++) { acc[i][j] = 0.f; tot[i][j] = 0.f; }

    const int tx = tid & 15;     // n direction
    const int ty = tid >> 4;     // m direction
    const int mo = ty * 8, no = tx * 8;

    int p = 0;
#pragma unroll 1
    for (int kt = 0; kt < NKT; ++kt) {
        if (kt + 1 < NKT) {
            const float* a2 = aP + (kt + 1) * BK;
            const float* b2 = bP + (kt + 1) * BK;
            ra0 = *(const float4*)(a2);
            ra1 = *(const float4*)(a2 + 64 * NIN);
            rb0 = *(const float4*)(b2);
            rb1 = *(const float4*)(b2 + 64 * NIN);
        }
#pragma unroll
        for (int k = 0; k < BK; k++) {
            float af[8], bf[8];
            *(float4*)&af[0] = *(const float4*)&a_s[p][k][mo];
            *(float4*)&af[4] = *(const float4*)&a_s[p][k][mo + 4];
            *(float4*)&bf[0] = *(const float4*)&b_s[p][k][no];
            *(float4*)&bf[4] = *(const float4*)&b_s[p][k][no + 4];
#pragma unroll
            for (int i = 0; i < 8; i++)
#pragma unroll
                for (int j = 0; j < 8; j++)
                    acc[i][j] = __fmaf_rn(af[i], bf[j], acc[i][j]);
        }
        // Eigen kc=400 panel boundary: fold chain into running total.
        const int kn = kt + 1;
        if (kn == 25 || kn == NKT) {
#pragma unroll
            for (int i = 0; i < 8; i++)
#pragma unroll
                for (int j = 0; j < 8; j++) {
                    tot[i][j] = __fadd_rn(tot[i][j], acc[i][j]);
                    acc[i][j] = 0.f;
                }
        }
        if (kt + 1 < NKT) {
            const int q = p ^ 1;
            a_s[q][lk + 0][lrow] = ra0.x; a_s[q][lk + 1][lrow] = ra0.y;
            a_s[q][lk + 2][lrow] = ra0.z; a_s[q][lk + 3][lrow] = ra0.w;
            a_s[q][lk + 0][lrow + 64] = ra1.x; a_s[q][lk + 1][lrow + 64] = ra1.y;
            a_s[q][lk + 2][lrow + 64] = ra1.z; a_s[q][lk + 3][lrow + 64] = ra1.w;
            b_s[q][lk + 0][lrow] = rb0.x; b_s[q][lk + 1][lrow] = rb0.y;
            b_s[q][lk + 2][lrow] = rb0.z; b_s[q][lk + 3][lrow] = rb0.w;
            b_s[q][lk + 0][lrow + 64] = rb1.x; b_s[q][lk + 1][lrow + 64] = rb1.y;
            b_s[q][lk + 2][lrow + 64] = rb1.z; b_s[q][lk + 3][lrow + 64] = rb1.w;
            __syncthreads();
            p = q;
        }
    }

#pragma unroll
    for (int i = 0; i < 8; i++) {
        size_t base = (size_t)(bm + mo + i) * NHID + bn + no;
#pragma unroll
        for (int j = 0; j < 8; j++)
            C[base + j] = __fadd_rn(tot[i][j], __ldg(&bias[bn + no + j]));
    }
}

// ---------------------------------------------------------------------------
// LIF layer 1: per-(b,h) scan over t; pack spikes as bitmasks via ballot.
// Exact reference op order: t1 = beta*mem; t2 = t1 + cur; mem = t2 - reset.
// ---------------------------------------------------------------------------
__global__ void __launch_bounds__(256)
lif1_kernel()
{
    const float* __restrict__ cur = g_cur1;
    unsigned* __restrict__ spk = g_spk1;
    const int idx  = blockIdx.x * 256 + threadIdx.x;   // b*1024 + h
    const int lane = threadIdx.x & 31;
    const int word = idx >> 5;                          // b*32 + h/32
    float mem = 0.f;
#pragma unroll 4
    for (int t = 0; t < T_STEPS; t++) {
        float c = cur[(size_t)t * (BATCH * NHID) + idx];
        float reset = (mem > 1.0f) ? 1.0f : 0.0f;
        mem = __fsub_rn(__fadd_rn(__fmul_rn(BETA, mem), c), reset);
        unsigned b = __ballot_sync(0xffffffffu, mem > 1.0f);
        if (lane == 0) spk[(size_t)t * (BATCH * NHID / 32) + word] = b;
    }
}

// ---------------------------------------------------------------------------
// GEMM2: cur2[t,b,o] over K=1024 with kc=344 panels:
// boundaries at h = 344, 688 (mid-word -> catch-up fold in walk).
// Within panel: ascending-h adds of spiking weights (fma with 0/1 is exact,
// so skipping zero terms preserves bits; empty panels fold exact +0.0).
// One warp per (t,b); all lanes walk the SAME mask (uniform control flow),
// lane o<10 owns output o. sw[h*10+o]: lanes 0..9 hit consecutive banks.
// ---------------------------------------------------------------------------
__global__ void __launch_bounds__(256)
gemm2_kernel(const float* __restrict__ w2, const float* __restrict__ b2)
{
    __shared__ float sw[NHID * NOUT];    // 40 KB, sw[h*10 + o]
    const unsigned* __restrict__ spk = g_spk1;
    float* __restrict__ cur2 = g_cur2;

    for (int i = threadIdx.x; i < NOUT * NHID; i += 256) {
        int o = i >> 10, h = i & 1023;
        sw[h * NOUT + o] = w2[i];
    }
    __syncthreads();

    const int gw   = (blockIdx.x * 256 + threadIdx.x) >> 5;  // t*512 + b
    const int lane = threadIdx.x & 31;

    const unsigned* mrow = spk + (size_t)gw * 32;
    float tot = 0.f;
    float acc = 0.f;
    int   nb  = KC2;                     // next panel boundary (344, 688)

#pragma unroll 1
    for (int w = 0; w < 32; w++) {
        unsigned m = mrow[w];            // identical across the warp
        while (m) {
            int j = __ffs(m) - 1;
            m &= (m - 1);
            int h = (w << 5) + j;        // ascending h
            while (h >= nb) {            // crossed panel boundary (maybe >1)
                tot = __fadd_rn(tot, acc);
                acc = 0.f;
                nb += KC2;
            }
            float wv = (lane < NOUT) ? sw[h * NOUT + lane] : 0.f;
            acc = __fadd_rn(acc, wv);
        }
    }
    tot = __fadd_rn(tot, acc);           // fold final panel

    if (lane < NOUT)
        cur2[(size_t)gw * NOUT + lane] = __fadd_rn(tot, __ldg(&b2[lane]));
}

// ---------------------------------------------------------------------------
// LIF layer 2: per-(b,o) scan over t; exact op order; write spk2 to d_out.
// ---------------------------------------------------------------------------
__global__ void __launch_bounds__(256)
lif2_kernel(float* __restrict__ out)
{
    const int idx = blockIdx.x * 256 + threadIdx.x;
    if (idx >= BATCH * NOUT) return;
    const float* __restrict__ c2 = g_cur2;
    float mem = 0.f;
#pragma unroll 4
    for (int t = 0; t < T_STEPS; t++) {
        float c = c2[(size_t)t * (BATCH * NOUT) + idx];
        float reset = (mem > 1.0f) ? 1.0f : 0.0f;
        mem = __fsub_rn(__fadd_rn(__fmul_rn(BETA, mem), c), reset);
        out[(size_t)t * (BATCH * NOUT) + idx] = (mem > 1.0f) ? 1.0f : 0.0f;
    }
}

// ---------------------------------------------------------------------------
extern "C" void kernel_launch(void* const* d_in, const int* in_sizes, int n_in,
                              void* d_out, int out_size)
{
    const float* data = (const float*)d_in[0];   // [200, 512, 784]
    const float* w1   = (const float*)d_in[1];   // [1024, 784]
    const float* b1   = (const float*)d_in[2];   // [1024]
    const float* w2   = (const float*)d_in[3];   // [10, 1024]
    const float* b2   = (const float*)d_in[4];   // [10]
    float* out = (float*)d_out;                  // [200, 512, 10]

    gemm1_kernel<<<dim3(NHID / BN, M_TOTAL / BM), 256>>>(data, w1, b1);
    lif1_kernel<<<(BATCH * NHID) / 256, 256>>>();
    gemm2_kernel<<<(M_TOTAL * 32) / 256, 256>>>(w2, b2);
    lif2_kernel<<<(BATCH * NOUT + 255) / 256, 256>>>(out);
}

// round 14
// speedup vs baseline: 1.1430x; 1.1430x over previous
#include <cuda_runtime.h>

// ---------------------------------------------------------------------------
// Net_33071248179899: 2-layer LIF SNN, T=200, B=512, 784->1024->10
// PASSING numerics (frozen): Eigen single-thread fold
//   K=784  -> panels {400, 384};  K=1024 -> panels {344, 344, 336}
//   per element: C = (p0 + p1)[+p2], pi = ascending-k fp32 FMA chain from 0,
//   bias added once at the end. LIF: ((beta*mem)+cur)-reset, separate ops.
// R14 perf: gemm1 inner loop moved to packed fma.rn.f32x2 (FFMA2) -- each
// half is an independent IEEE fp32 FMA/rn => bit-identical fold, 2x fp32 rate.
// ---------------------------------------------------------------------------

constexpr int T_STEPS = 200;
constexpr int BATCH   = 512;
constexpr int NIN     = 784;
constexpr int NHID    = 1024;
constexpr int NOUT    = 10;
constexpr int M_TOTAL = T_STEPS * BATCH;          // 102400
constexpr float BETA  = 0.95f;
constexpr int KC2     = 344;                       // Eigen single-thread kc, K=1024

// Scratch (device globals: allocation-free rule)
__device__ float    g_cur1[(size_t)M_TOTAL * NHID];           // ~420 MB
__device__ unsigned g_spk1[(size_t)M_TOTAL * (NHID / 32)];    // ~13 MB
__device__ float    g_cur2[(size_t)M_TOTAL * NOUT];           // ~4 MB

// ---- packed f32x2 helpers (each half = independent fp32 op, rn) ----------
__device__ __forceinline__ unsigned long long pack2(float lo, float hi) {
    unsigned long long r;
    asm("mov.b64 %0, {%1, %2};"
        : "=l"(r) : "r"(__float_as_uint(lo)), "r"(__float_as_uint(hi)));
    return r;
}
__device__ __forceinline__ unsigned long long fma2(unsigned long long a,
                                                   unsigned long long b,
                                                   unsigned long long c) {
    unsigned long long d;
    asm("fma.rn.f32x2 %0, %1, %2, %3;" : "=l"(d) : "l"(a), "l"(b), "l"(c));
    return d;
}
__device__ __forceinline__ unsigned long long add2(unsigned long long a,
                                                   unsigned long long b) {
    unsigned long long d;
    asm("add.rn.f32x2 %0, %1, %2;" : "=l"(d) : "l"(a), "l"(b));
    return d;
}

// ---------------------------------------------------------------------------
// GEMM1: Eigen-fold GEMM, FFMA2 inner loop. Tiles 128x128x16, 256 threads,
// 8x8/thread (as 8x4 packed pairs), double-buffered smem.
// kc=400 boundary: fold after kt=25 (k=400) and at the end (384-tail).
// ---------------------------------------------------------------------------
constexpr int BM = 128, BN = 128, BK = 16;
constexpr int NKT = NIN / BK;   // 49

__global__ void __launch_bounds__(256, 1)
gemm1_kernel(const float* __restrict__ A, const float* __restrict__ W,
             const float* __restrict__ bias)
{
    __shared__ float a_s[2][BK][BM + 4];
    __shared__ float b_s[2][BK][BN + 4];
    float* __restrict__ C = g_cur1;

    const int tid = threadIdx.x;
    const int bm = blockIdx.y * BM;
    const int bn = blockIdx.x * BN;

    const int lrow = tid >> 2;          // 0..63
    const int lk   = (tid & 3) * 4;     // 0,4,8,12

    const float* aP = A + (size_t)(bm + lrow) * NIN + lk;
    const float* bP = W + (size_t)(bn + lrow) * NIN + lk;

    float4 ra0, ra1, rb0, rb1;

    ra0 = *(const float4*)(aP);
    ra1 = *(const float4*)(aP + 64 * NIN);
    rb0 = *(const float4*)(bP);
    rb1 = *(const float4*)(bP + 64 * NIN);

    a_s[0][lk + 0][lrow] = ra0.x; a_s[0][lk + 1][lrow] = ra0.y;
    a_s[0][lk + 2][lrow] = ra0.z; a_s[0][lk + 3][lrow] = ra0.w;
    a_s[0][lk + 0][lrow + 64] = ra1.x; a_s[0][lk + 1][lrow + 64] = ra1.y;
    a_s[0][lk + 2][lrow + 64] = ra1.z; a_s[0][lk + 3][lrow + 64] = ra1.w;
    b_s[0][lk + 0][lrow] = rb0.x; b_s[0][lk + 1][lrow] = rb0.y;
    b_s[0][lk + 2][lrow] = rb0.z; b_s[0][lk + 3][lrow] = rb0.w;
    b_s[0][lk + 0][lrow + 64] = rb1.x; b_s[0][lk + 1][lrow + 64] = rb1.y;
    b_s[0][lk + 2][lrow + 64] = rb1.z; b_s[0][lk + 3][lrow + 64] = rb1.w;
    __syncthreads();

    // 8x8 fp32 accumulators as 8x4 packed f32x2 pairs (pair = cols 2jp,2jp+1)
    unsigned long long acc2[8][4];   // current k-panel FMA chain
    unsigned long long tot2[8][4];   // running cross-panel sum
#pragma unroll
    for (int i = 0; i < 8; i++)
#pragma unroll
        for (int jp = 0; jp < 4; jp++) { acc2[i][jp] = 0ull; tot2[i][jp] = 0ull; }

    const int tx = tid & 15;     // n direction
    const int ty = tid >> 4;     // m direction
    const int mo = ty * 8, no = tx * 8;

    int p = 0;
#pragma unroll 1
    for (int kt = 0; kt < NKT; ++kt) {
        if (kt + 1 < NKT) {
            const float* a2 = aP + (kt + 1) * BK;
            const float* b2 = bP + (kt + 1) * BK;
            ra0 = *(const float4*)(a2);
            ra1 = *(const float4*)(a2 + 64 * NIN);
            rb0 = *(const float4*)(b2);
            rb1 = *(const float4*)(b2 + 64 * NIN);
        }
#pragma unroll
        for (int k = 0; k < BK; k++) {
            float af[8], bf[8];
            *(float4*)&af[0] = *(const float4*)&a_s[p][k][mo];
            *(float4*)&af[4] = *(const float4*)&a_s[p][k][mo + 4];
            *(float4*)&bf[0] = *(const float4*)&b_s[p][k][no];
            *(float4*)&bf[4] = *(const float4*)&b_s[p][k][no + 4];

            unsigned long long aa[8], bb[4];
#pragma unroll
            for (int i = 0; i < 8; i++) aa[i] = pack2(af[i], af[i]);
#pragma unroll
            for (int jp = 0; jp < 4; jp++) bb[jp] = pack2(bf[2*jp], bf[2*jp+1]);
#pragma unroll
            for (int i = 0; i < 8; i++)
#pragma unroll
                for (int jp = 0; jp < 4; jp++)
                    acc2[i][jp] = fma2(aa[i], bb[jp], acc2[i][jp]);
        }
        // Eigen kc=400 panel boundary: fold chain into running total.
        const int kn = kt + 1;
        if (kn == 25 || kn == NKT) {
#pragma unroll
            for (int i = 0; i < 8; i++)
#pragma unroll
                for (int jp = 0; jp < 4; jp++) {
                    tot2[i][jp] = add2(tot2[i][jp], acc2[i][jp]);
                    acc2[i][jp] = 0ull;
                }
        }
        if (kt + 1 < NKT) {
            const int q = p ^ 1;
            a_s[q][lk + 0][lrow] = ra0.x; a_s[q][lk + 1][lrow] = ra0.y;
            a_s[q][lk + 2][lrow] = ra0.z; a_s[q][lk + 3][lrow] = ra0.w;
            a_s[q][lk + 0][lrow + 64] = ra1.x; a_s[q][lk + 1][lrow + 64] = ra1.y;
            a_s[q][lk + 2][lrow + 64] = ra1.z; a_s[q][lk + 3][lrow + 64] = ra1.w;
            b_s[q][lk + 0][lrow] = rb0.x; b_s[q][lk + 1][lrow] = rb0.y;
            b_s[q][lk + 2][lrow] = rb0.z; b_s[q][lk + 3][lrow] = rb0.w;
            b_s[q][lk + 0][lrow + 64] = rb1.x; b_s[q][lk + 1][lrow + 64] = rb1.y;
            b_s[q][lk + 2][lrow + 64] = rb1.z; b_s[q][lk + 3][lrow + 64] = rb1.w;
            __syncthreads();
            p = q;
        }
    }

    // Epilogue: C = tot + bias (packed; each half an independent rn add),
    // stored as aligned 8-byte pairs (no, bn multiples of 8 -> even cols).
#pragma unroll
    for (int i = 0; i < 8; i++) {
        size_t base = (size_t)(bm + mo + i) * NHID + bn + no;
#pragma unroll
        for (int jp = 0; jp < 4; jp++) {
            unsigned long long bias2 =
                pack2(__ldg(&bias[bn + no + 2*jp]), __ldg(&bias[bn + no + 2*jp + 1]));
            *(unsigned long long*)&C[base + 2*jp] = add2(tot2[i][jp], bias2);
        }
    }
}

// ---------------------------------------------------------------------------
// LIF layer 1: per-(b,h) scan over t; pack spikes as bitmasks via ballot.
// Exact reference op order: t1 = beta*mem; t2 = t1 + cur; mem = t2 - reset.
// ---------------------------------------------------------------------------
__global__ void __launch_bounds__(256)
lif1_kernel()
{
    const float* __restrict__ cur = g_cur1;
    unsigned* __restrict__ spk = g_spk1;
    const int idx  = blockIdx.x * 256 + threadIdx.x;   // b*1024 + h
    const int lane = threadIdx.x & 31;
    const int word = idx >> 5;                          // b*32 + h/32
    float mem = 0.f;
#pragma unroll 4
    for (int t = 0; t < T_STEPS; t++) {
        float c = cur[(size_t)t * (BATCH * NHID) + idx];
        float reset = (mem > 1.0f) ? 1.0f : 0.0f;
        mem = __fsub_rn(__fadd_rn(__fmul_rn(BETA, mem), c), reset);
        unsigned b = __ballot_sync(0xffffffffu, mem > 1.0f);
        if (lane == 0) spk[(size_t)t * (BATCH * NHID / 32) + word] = b;
    }
}

// ---------------------------------------------------------------------------
// GEMM2: cur2[t,b,o] over K=1024 with kc=344 panels:
// boundaries at h = 344, 688 (mid-word -> catch-up fold in walk).
// Within panel: ascending-h adds of spiking weights (fma with 0/1 is exact,
// so skipping zero terms preserves bits; empty panels fold exact +0.0).
// One warp per (t,b); all lanes walk the SAME mask (uniform control flow),
// lane o<10 owns output o. sw[h*10+o]: lanes 0..9 hit consecutive banks.
// ---------------------------------------------------------------------------
__global__ void __launch_bounds__(256)
gemm2_kernel(const float* __restrict__ w2, const float* __restrict__ b2)
{
    __shared__ float sw[NHID * NOUT];    // 40 KB, sw[h*10 + o]
    const unsigned* __restrict__ spk = g_spk1;
    float* __restrict__ cur2 = g_cur2;

    for (int i = threadIdx.x; i < NOUT * NHID; i += 256) {
        int o = i >> 10, h = i & 1023;
        sw[h * NOUT + o] = w2[i];
    }
    __syncthreads();

    const int gw   = (blockIdx.x * 256 + threadIdx.x) >> 5;  // t*512 + b
    const int lane = threadIdx.x & 31;

    const unsigned* mrow = spk + (size_t)gw * 32;
    float tot = 0.f;
    float acc = 0.f;
    int   nb  = KC2;                     // next panel boundary (344, 688)

#pragma unroll 1
    for (int w = 0; w < 32; w++) {
        unsigned m = mrow[w];            // identical across the warp
        while (m) {
            int j = __ffs(m) - 1;
            m &= (m - 1);
            int h = (w << 5) + j;        // ascending h
            while (h >= nb) {            // crossed panel boundary (maybe >1)
                tot = __fadd_rn(tot, acc);
                acc = 0.f;
                nb += KC2;
            }
            float wv = (lane < NOUT) ? sw[h * NOUT + lane] : 0.f;
            acc = __fadd_rn(acc, wv);
        }
    }
    tot = __fadd_rn(tot, acc);           // fold final panel

    if (lane < NOUT)
        cur2[(size_t)gw * NOUT + lane] = __fadd_rn(tot, __ldg(&b2[lane]));
}

// ---------------------------------------------------------------------------
// LIF layer 2: per-(b,o) scan over t; exact op order; write spk2 to d_out.
// ---------------------------------------------------------------------------
__global__ void __launch_bounds__(256)
lif2_kernel(float* __restrict__ out)
{
    const int idx = blockIdx.x * 256 + threadIdx.x;
    if (idx >= BATCH * NOUT) return;
    const float* __restrict__ c2 = g_cur2;
    float mem = 0.f;
#pragma unroll 4
    for (int t = 0; t < T_STEPS; t++) {
        float c = c2[(size_t)t * (BATCH * NOUT) + idx];
        float reset = (mem > 1.0f) ? 1.0f : 0.0f;
        mem = __fsub_rn(__fadd_rn(__fmul_rn(BETA, mem), c), reset);
        out[(size_t)t * (BATCH * NOUT) + idx] = (mem > 1.0f) ? 1.0f : 0.0f;
    }
}

// ---------------------------------------------------------------------------
extern "C" void kernel_launch(void* const* d_in, const int* in_sizes, int n_in,
                              void* d_out, int out_size)
{
    const float* data = (const float*)d_in[0];   // [200, 512, 784]
    const float* w1   = (const float*)d_in[1];   // [1024, 784]
    const float* b1   = (const float*)d_in[2];   // [1024]
    const float* w2   = (const float*)d_in[3];   // [10, 1024]
    const float* b2   = (const float*)d_in[4];   // [10]
    float* out = (float*)d_out;                  // [200, 512, 10]

    gemm1_kernel<<<dim3(NHID / BN, M_TOTAL / BM), 256>>>(data, w1, b1);
    lif1_kernel<<<(BATCH * NHID) / 256, 256>>>();
    gemm2_kernel<<<(M_TOTAL * 32) / 256, 256>>>(w2, b2);
    lif2_kernel<<<(BATCH * NOUT + 255) / 256, 256>>>(out);
}